// round 1
// baseline (speedup 1.0000x reference)
#include <cuda_runtime.h>
#include <cuda_bf16.h>

#define Bc 8
#define Nc 1024
#define Hc 512
#define NHEADS 8
#define HD 64
#define MASK_VAL (-16384.0f)
#define LN_EPS 1e-5f

// ---------------- scratch (allocation-free rule: __device__ globals) ----------
__device__ float g_q[Bc * Nc * Hc];
__device__ float g_k[Bc * Nc * Hc];
__device__ float g_v[Bc * Nc * Hc];
__device__ float g_P[(size_t)Bc * NHEADS * Nc * Nc];   // 256 MB
__device__ float g_z0[Bc * NHEADS * Nc * HD];          // z_init (head-major v)
__device__ float g_zA[Bc * NHEADS * Nc * HD];
__device__ float g_zB[Bc * NHEADS * Nc * HD];

// ---------------- kernel 1: Y[8192,512] = X @ W^T + bias ---------------------
// 64x64 tile, BK=16, 256 threads, 4x4 micro-tile per thread.
__global__ __launch_bounds__(256) void gemm_qkv(
    const float* __restrict__ X, const float* __restrict__ W,
    const float* __restrict__ bias, float* __restrict__ Y)
{
    __shared__ float As[16][65];
    __shared__ float Bs[16][65];
    const int tx = threadIdx.x;
    const int tr = tx >> 4, tc = tx & 15;
    const int rowBase = blockIdx.y * 64;
    const int colBase = blockIdx.x * 64;

    float acc[4][4] = {};

    for (int k0 = 0; k0 < Hc; k0 += 16) {
        #pragma unroll
        for (int i = tx; i < 64 * 16; i += 256) {
            int m = i >> 4, kk = i & 15;
            As[kk][m] = X[(size_t)(rowBase + m) * Hc + k0 + kk];
            Bs[kk][m] = W[(size_t)(colBase + m) * Hc + k0 + kk];
        }
        __syncthreads();
        #pragma unroll
        for (int kk = 0; kk < 16; kk++) {
            float a[4], b[4];
            #pragma unroll
            for (int i = 0; i < 4; i++) a[i] = As[kk][tr * 4 + i];
            #pragma unroll
            for (int j = 0; j < 4; j++) b[j] = Bs[kk][tc * 4 + j];
            #pragma unroll
            for (int i = 0; i < 4; i++)
                #pragma unroll
                for (int j = 0; j < 4; j++)
                    acc[i][j] = fmaf(a[i], b[j], acc[i][j]);
        }
        __syncthreads();
    }
    #pragma unroll
    for (int i = 0; i < 4; i++)
        #pragma unroll
        for (int j = 0; j < 4; j++) {
            int r = rowBase + tr * 4 + i, c = colBase + tc * 4 + j;
            Y[(size_t)r * Hc + c] = acc[i][j] + bias[c];
        }
}

// ---------------- kernel 2: repack v -> head-major z_init --------------------
__global__ __launch_bounds__(256) void repack_v(
    const float* __restrict__ v, float* __restrict__ z0)
{
    size_t i = (size_t)blockIdx.x * 256 + threadIdx.x;  // [b][h][n][d]
    int d = i & (HD - 1);
    size_t t = i / HD;
    int n = t & (Nc - 1);
    size_t t2 = t / Nc;
    int h = t2 & (NHEADS - 1);
    int b = (int)(t2 / NHEADS);
    z0[i] = v[((size_t)b * Nc + n) * Hc + h * HD + d];
}

// ---------------- kernel 3: scores tile + adjacency mask ---------------------
// per (bh, ntile64, mtile64): S = Qh @ Kh^T over d=64, masked write into P.
__global__ __launch_bounds__(256) void scores_kernel(
    const float* __restrict__ q, const float* __restrict__ k,
    const int* __restrict__ adj, float* __restrict__ P)
{
    const int bh = blockIdx.z;
    const int b = bh >> 3, h = bh & 7;
    const int nBase = blockIdx.y * 64;
    const int mBase = blockIdx.x * 64;

    __shared__ float Qs[16][65];
    __shared__ float Ks[16][65];
    const int tx = threadIdx.x;
    const int tr = tx >> 4, tc = tx & 15;

    const float* qb = q + (size_t)b * Nc * Hc + h * HD;
    const float* kb = k + (size_t)b * Nc * Hc + h * HD;

    float acc[4][4] = {};
    for (int k0 = 0; k0 < HD; k0 += 16) {
        #pragma unroll
        for (int i = tx; i < 64 * 16; i += 256) {
            int r = i >> 4, kk = i & 15;
            Qs[kk][r] = qb[(size_t)(nBase + r) * Hc + k0 + kk];
            Ks[kk][r] = kb[(size_t)(mBase + r) * Hc + k0 + kk];
        }
        __syncthreads();
        #pragma unroll
        for (int kk = 0; kk < 16; kk++) {
            float a[4], bb[4];
            #pragma unroll
            for (int i = 0; i < 4; i++) a[i] = Qs[kk][tr * 4 + i];
            #pragma unroll
            for (int j = 0; j < 4; j++) bb[j] = Ks[kk][tc * 4 + j];
            #pragma unroll
            for (int i = 0; i < 4; i++)
                #pragma unroll
                for (int j = 0; j < 4; j++)
                    acc[i][j] = fmaf(a[i], bb[j], acc[i][j]);
        }
        __syncthreads();
    }
    const int* adjb = adj + (size_t)b * Nc * Nc;
    float* Pb = P + (size_t)bh * Nc * Nc;
    #pragma unroll
    for (int i = 0; i < 4; i++)
        #pragma unroll
        for (int j = 0; j < 4; j++) {
            int nn = nBase + tr * 4 + i, mm = mBase + tc * 4 + j;
            int a = adjb[(size_t)nn * Nc + mm];
            Pb[(size_t)nn * Nc + mm] = (a == 0) ? MASK_VAL : acc[i][j];
        }
}

// ---------------- kernel 4: row softmax in place -----------------------------
__global__ __launch_bounds__(256) void softmax_kernel(float* __restrict__ P)
{
    float* p = P + (size_t)blockIdx.x * Nc;
    __shared__ float red[256];
    const int t = threadIdx.x;

    float v[4];
    float mx = -3.0e38f;
    #pragma unroll
    for (int j = 0; j < 4; j++) { v[j] = p[t + j * 256]; mx = fmaxf(mx, v[j]); }
    red[t] = mx; __syncthreads();
    #pragma unroll
    for (int s = 128; s > 0; s >>= 1) {
        if (t < s) red[t] = fmaxf(red[t], red[t + s]);
        __syncthreads();
    }
    mx = red[0]; __syncthreads();

    float sum = 0.f;
    #pragma unroll
    for (int j = 0; j < 4; j++) { v[j] = __expf(v[j] - mx); sum += v[j]; }
    red[t] = sum; __syncthreads();
    #pragma unroll
    for (int s = 128; s > 0; s >>= 1) {
        if (t < s) red[t] += red[t + s];
        __syncthreads();
    }
    float inv = 1.0f / red[0];
    #pragma unroll
    for (int j = 0; j < 4; j++) p[t + j * 256] = v[j] * inv;
}

// ---------------- kernel 5: one hop  zout = 0.9*P@z + 0.1*z_init -------------
// per (bh, ntile128): [128 x 64] output, BK=16, 256 threads, 8x4 micro.
__global__ __launch_bounds__(256) void hop_kernel(
    const float* __restrict__ Pg, const float* __restrict__ zin,
    const float* __restrict__ zinit, float* __restrict__ zout)
{
    const int bh = blockIdx.y;
    const int nBase = blockIdx.x * 128;
    const float* Pp = Pg + (size_t)bh * Nc * Nc;
    const float* zi = zin + (size_t)bh * Nc * HD;
    const float* z0 = zinit + (size_t)bh * Nc * HD;
    float* zo = zout + (size_t)bh * Nc * HD;

    __shared__ float Ps[16][129];
    __shared__ float Zs[16][65];
    const int tx = threadIdx.x;
    const int tr = tx >> 4, tc = tx & 15;

    float acc[8][4] = {};
    for (int k0 = 0; k0 < Nc; k0 += 16) {
        #pragma unroll
        for (int i = tx; i < 128 * 16; i += 256) {
            int r = i >> 4, kk = i & 15;
            Ps[kk][r] = Pp[(size_t)(nBase + r) * Nc + k0 + kk];
        }
        #pragma unroll
        for (int i = tx; i < 16 * 64; i += 256) {
            int r = i >> 6, c = i & 63;
            Zs[r][c] = zi[(size_t)(k0 + r) * HD + c];
        }
        __syncthreads();
        #pragma unroll
        for (int kk = 0; kk < 16; kk++) {
            float a[8], bv[4];
            #pragma unroll
            for (int i = 0; i < 8; i++) a[i] = Ps[kk][tr * 8 + i];
            #pragma unroll
            for (int j = 0; j < 4; j++) bv[j] = Zs[kk][tc * 4 + j];
            #pragma unroll
            for (int i = 0; i < 8; i++)
                #pragma unroll
                for (int j = 0; j < 4; j++)
                    acc[i][j] = fmaf(a[i], bv[j], acc[i][j]);
        }
        __syncthreads();
    }
    #pragma unroll
    for (int i = 0; i < 8; i++)
        #pragma unroll
        for (int j = 0; j < 4; j++) {
            int nn = nBase + tr * 8 + i, dd = tc * 4 + j;
            size_t idx = (size_t)nn * HD + dd;
            zo[idx] = 0.9f * acc[i][j] + 0.1f * z0[idx];
        }
}

// ---------------- kernel 6: residual + layernorm -----------------------------
__global__ __launch_bounds__(256) void out_kernel(
    const float* __restrict__ x, const float* __restrict__ z,
    const float* __restrict__ gamma, const float* __restrict__ beta,
    float* __restrict__ out)
{
    const int row = blockIdx.x;          // b*N + n
    const int b = row >> 10, n = row & (Nc - 1);
    const int t = threadIdx.x;
    __shared__ float red[256];

    float y[2];
    float s = 0.f;
    #pragma unroll
    for (int j = 0; j < 2; j++) {
        int idx = t + j * 256;
        int h = idx >> 6, d = idx & 63;
        y[j] = x[(size_t)row * Hc + idx] +
               z[(((size_t)b * NHEADS + h) * Nc + n) * HD + d];
        s += y[j];
    }
    red[t] = s; __syncthreads();
    #pragma unroll
    for (int st = 128; st > 0; st >>= 1) {
        if (t < st) red[t] += red[t + st];
        __syncthreads();
    }
    float mu = red[0] * (1.0f / Hc);
    __syncthreads();

    float vs = 0.f;
    #pragma unroll
    for (int j = 0; j < 2; j++) { float d0 = y[j] - mu; vs += d0 * d0; }
    red[t] = vs; __syncthreads();
    #pragma unroll
    for (int st = 128; st > 0; st >>= 1) {
        if (t < st) red[t] += red[t + st];
        __syncthreads();
    }
    float var = red[0] * (1.0f / Hc);
    float rstd = rsqrtf(var + LN_EPS);
    #pragma unroll
    for (int j = 0; j < 2; j++) {
        int idx = t + j * 256;
        out[(size_t)row * Hc + idx] = (y[j] - mu) * rstd * gamma[idx] + beta[idx];
    }
}

// ---------------- launch -----------------------------------------------------
extern "C" void kernel_launch(void* const* d_in, const int* in_sizes, int n_in,
                              void* d_out, int out_size)
{
    const float* x     = (const float*)d_in[0];
    const int*   adj   = (const int*)d_in[1];
    const float* Wq    = (const float*)d_in[2];
    const float* bq    = (const float*)d_in[3];
    const float* Wk    = (const float*)d_in[4];
    const float* bk    = (const float*)d_in[5];
    const float* Wv    = (const float*)d_in[6];
    const float* bv    = (const float*)d_in[7];
    const float* gamma = (const float*)d_in[8];
    const float* beta  = (const float*)d_in[9];
    float* out = (float*)d_out;

    float *pq, *pk, *pv, *pP, *pz0, *pzA, *pzB;
    cudaGetSymbolAddress((void**)&pq,  g_q);
    cudaGetSymbolAddress((void**)&pk,  g_k);
    cudaGetSymbolAddress((void**)&pv,  g_v);
    cudaGetSymbolAddress((void**)&pP,  g_P);
    cudaGetSymbolAddress((void**)&pz0, g_z0);
    cudaGetSymbolAddress((void**)&pzA, g_zA);
    cudaGetSymbolAddress((void**)&pzB, g_zB);

    dim3 gGemm(Hc / 64, (Bc * Nc) / 64);          // (8, 128)
    gemm_qkv<<<gGemm, 256>>>(x, Wq, bq, pq);
    gemm_qkv<<<gGemm, 256>>>(x, Wk, bk, pk);
    gemm_qkv<<<gGemm, 256>>>(x, Wv, bv, pv);

    repack_v<<<(Bc * Nc * Hc) / 256, 256>>>(pv, pz0);

    dim3 gScores(Nc / 64, Nc / 64, Bc * NHEADS);  // (16, 16, 64)
    scores_kernel<<<gScores, 256>>>(pq, pk, adj, pP);

    softmax_kernel<<<Bc * NHEADS * Nc, 256>>>(pP);

    dim3 gHop(Nc / 128, Bc * NHEADS);             // (8, 64)
    hop_kernel<<<gHop, 256>>>(pP, pz0, pz0, pzA);
    hop_kernel<<<gHop, 256>>>(pP, pzA, pz0, pzB);
    hop_kernel<<<gHop, 256>>>(pP, pzB, pz0, pzA);
    hop_kernel<<<gHop, 256>>>(pP, pzA, pz0, pzB);

    out_kernel<<<Bc * Nc, 256>>>(x, pzB, gamma, beta, out);
}

// round 2
// speedup vs baseline: 2.7658x; 2.7658x over previous
#include <cuda_runtime.h>
#include <cuda_bf16.h>

#define Bc 8
#define Nc 1024
#define Hc 512
#define NHEADS 8
#define HD 64
#define LN_EPS 1e-5f

// ---------------- scratch (allocation-free rule: __device__ globals) ----------
__device__ float g_q[Bc * NHEADS * Nc * HD];            // head-major [bh][n][d]
__device__ float g_k[Bc * NHEADS * Nc * HD];
__device__ float g_z0[Bc * NHEADS * Nc * HD];           // v head-major = z_init
__device__ float g_P[(size_t)Bc * NHEADS * Nc * Nc];    // unnormalized exp(scores)
__device__ float g_rowsum[Bc * NHEADS * Nc];
__device__ float g_zA[Bc * NHEADS * Nc * HD];
__device__ float g_zB[Bc * NHEADS * Nc * HD];

// ---------------- mma helpers ------------------------------------------------
__device__ __forceinline__ unsigned f2tf(float x) {
    unsigned r;
    asm("cvt.rna.tf32.f32 %0, %1;" : "=r"(r) : "f"(x));
    return r;
}
__device__ __forceinline__ void mma_tf32(float c[4],
    unsigned a0, unsigned a1, unsigned a2, unsigned a3,
    unsigned b0, unsigned b1)
{
    asm("mma.sync.aligned.m16n8k8.row.col.f32.tf32.tf32.f32 "
        "{%0,%1,%2,%3},{%4,%5,%6,%7},{%8,%9},{%0,%1,%2,%3};"
        : "+f"(c[0]), "+f"(c[1]), "+f"(c[2]), "+f"(c[3])
        : "r"(a0), "r"(a1), "r"(a2), "r"(a3), "r"(b0), "r"(b1));
}

// ---------------- kernel 1: fused QKV GEMM, head-major output ----------------
// y[m][n] = sum_k X[m][k] * W[n][k] + bias[n];  out[bh][ntok][d]
// grid (8 ntile, 64 mtile, 3 which), block 256 (8 warps, 4x2, warp 32x32)
__global__ __launch_bounds__(256) void qkv_kernel(
    const float* __restrict__ X,
    const float* __restrict__ Wq, const float* __restrict__ bq,
    const float* __restrict__ Wk, const float* __restrict__ bk,
    const float* __restrict__ Wv, const float* __restrict__ bv,
    float* __restrict__ outq, float* __restrict__ outk, float* __restrict__ outv)
{
    const int which = blockIdx.z;
    const float* W    = which == 0 ? Wq : which == 1 ? Wk : Wv;
    const float* bias = which == 0 ? bq : which == 1 ? bk : bv;
    float* out        = which == 0 ? outq : which == 1 ? outk : outv;

    __shared__ float Xs[128][36];
    __shared__ float Ws[64][36];

    const int tid = threadIdx.x;
    const int wid = tid >> 5, lane = tid & 31;
    const int g = lane >> 2, t = lane & 3;
    const int warpM = (wid >> 1) * 32;
    const int warpN = (wid & 1) * 32;
    const int mBase = blockIdx.y * 128;
    const int nBase = blockIdx.x * 64;

    float acc[2][4][4] = {};

    for (int k0 = 0; k0 < Hc; k0 += 32) {
        #pragma unroll
        for (int it = 0; it < 4; it++) {
            int j = tid + it * 256;          // 0..1023 float4s of X tile
            int r = j >> 3, c4 = (j & 7) * 4;
            *(float4*)&Xs[r][c4] = *(const float4*)&X[(size_t)(mBase + r) * Hc + k0 + c4];
        }
        #pragma unroll
        for (int it = 0; it < 2; it++) {
            int j = tid + it * 256;          // 0..511 float4s of W tile
            int r = j >> 3, c4 = (j & 7) * 4;
            *(float4*)&Ws[r][c4] = *(const float4*)&W[(size_t)(nBase + r) * Hc + k0 + c4];
        }
        __syncthreads();
        #pragma unroll
        for (int ks = 0; ks < 32; ks += 8) {
            unsigned a[2][4], b[4][2];
            #pragma unroll
            for (int mf = 0; mf < 2; mf++) {
                int r0 = warpM + mf * 16 + g;
                a[mf][0] = f2tf(Xs[r0][ks + t]);
                a[mf][1] = f2tf(Xs[r0 + 8][ks + t]);
                a[mf][2] = f2tf(Xs[r0][ks + t + 4]);
                a[mf][3] = f2tf(Xs[r0 + 8][ks + t + 4]);
            }
            #pragma unroll
            for (int nf = 0; nf < 4; nf++) {
                int nr = warpN + nf * 8 + g;
                b[nf][0] = f2tf(Ws[nr][ks + t]);
                b[nf][1] = f2tf(Ws[nr][ks + t + 4]);
            }
            #pragma unroll
            for (int mf = 0; mf < 2; mf++)
                #pragma unroll
                for (int nf = 0; nf < 4; nf++)
                    mma_tf32(acc[mf][nf], a[mf][0], a[mf][1], a[mf][2], a[mf][3],
                             b[nf][0], b[nf][1]);
        }
        __syncthreads();
    }

    #pragma unroll
    for (int mf = 0; mf < 2; mf++)
        #pragma unroll
        for (int nf = 0; nf < 4; nf++)
            #pragma unroll
            for (int e = 0; e < 4; e++) {
                int row = mBase + warpM + mf * 16 + g + ((e >> 1) * 8);
                int col = nBase + warpN + nf * 8 + 2 * t + (e & 1);
                float val = acc[mf][nf][e] + bias[col];
                int btok = row >> 10, ntok = row & 1023;
                int h = col >> 6, d = col & 63;
                out[(((size_t)btok * NHEADS + h) * Nc + ntok) * HD + d] = val;
            }
}

// ---------------- kernel 2: scores -> masked exp + rowsum --------------------
// grid (8 coltile, 8 rowtile, 64 bh), block 256 (8 warps, 2x4, warp 64x32)
__global__ __launch_bounds__(256) void scores_kernel(
    const float* __restrict__ q, const float* __restrict__ k,
    const int* __restrict__ adj, float* __restrict__ P,
    float* __restrict__ rowsum)
{
    const int bh = blockIdx.z;
    const int b = bh >> 3;
    const int nBase = blockIdx.y * 128;   // query rows
    const int mBase = blockIdx.x * 128;   // key cols

    __shared__ float Qs[128][36];
    __shared__ float Ks[128][36];

    const int tid = threadIdx.x;
    const int wid = tid >> 5, lane = tid & 31;
    const int g = lane >> 2, t = lane & 3;
    const int warpM = (wid >> 2) * 64;
    const int warpN = (wid & 3) * 32;

    const float* qb = q + (size_t)bh * Nc * HD;
    const float* kb = k + (size_t)bh * Nc * HD;

    float acc[4][4][4] = {};

    for (int k0 = 0; k0 < HD; k0 += 32) {
        #pragma unroll
        for (int it = 0; it < 4; it++) {
            int j = tid + it * 256;
            int r = j >> 3, c4 = (j & 7) * 4;
            *(float4*)&Qs[r][c4] = *(const float4*)&qb[(size_t)(nBase + r) * HD + k0 + c4];
            *(float4*)&Ks[r][c4] = *(const float4*)&kb[(size_t)(mBase + r) * HD + k0 + c4];
        }
        __syncthreads();
        #pragma unroll
        for (int ks = 0; ks < 32; ks += 8) {
            unsigned a[4][4], bb[4][2];
            #pragma unroll
            for (int mf = 0; mf < 4; mf++) {
                int r0 = warpM + mf * 16 + g;
                a[mf][0] = f2tf(Qs[r0][ks + t]);
                a[mf][1] = f2tf(Qs[r0 + 8][ks + t]);
                a[mf][2] = f2tf(Qs[r0][ks + t + 4]);
                a[mf][3] = f2tf(Qs[r0 + 8][ks + t + 4]);
            }
            #pragma unroll
            for (int nf = 0; nf < 4; nf++) {
                int nr = warpN + nf * 8 + g;
                bb[nf][0] = f2tf(Ks[nr][ks + t]);
                bb[nf][1] = f2tf(Ks[nr][ks + t + 4]);
            }
            #pragma unroll
            for (int mf = 0; mf < 4; mf++)
                #pragma unroll
                for (int nf = 0; nf < 4; nf++)
                    mma_tf32(acc[mf][nf], a[mf][0], a[mf][1], a[mf][2], a[mf][3],
                             bb[nf][0], bb[nf][1]);
        }
        __syncthreads();
    }

    const int* adjb = adj + (size_t)b * Nc * Nc;
    float* Pb = P + (size_t)bh * Nc * Nc;

    #pragma unroll
    for (int mf = 0; mf < 4; mf++) {
        #pragma unroll
        for (int half = 0; half < 2; half++) {
            int row = nBase + warpM + mf * 16 + g + half * 8;
            float local = 0.f;
            #pragma unroll
            for (int nf = 0; nf < 4; nf++) {
                int col = mBase + warpN + nf * 8 + 2 * t;
                float s0 = acc[mf][nf][half * 2 + 0];
                float s1 = acc[mf][nf][half * 2 + 1];
                int a0 = adjb[(size_t)row * Nc + col];
                int a1 = adjb[(size_t)row * Nc + col + 1];
                float e0 = a0 ? __expf(s0) : 0.f;
                float e1 = a1 ? __expf(s1) : 0.f;
                *(float2*)&Pb[(size_t)row * Nc + col] = make_float2(e0, e1);
                local += e0 + e1;
            }
            local += __shfl_xor_sync(0xffffffffu, local, 1);
            local += __shfl_xor_sync(0xffffffffu, local, 2);
            if (t == 0) atomicAdd(&rowsum[(size_t)bh * Nc + row], local);
        }
    }
}

// ---------------- kernel 3: one hop  zout = 0.9*(P z)/rowsum + 0.1*z0 --------
// grid (8 mtile, 64 bh), block 256 (8 warps, 4x2, warp 32x32)
__global__ __launch_bounds__(256) void hop_kernel(
    const float* __restrict__ Pg, const float* __restrict__ rowsum,
    const float* __restrict__ zin, const float* __restrict__ zinit,
    float* __restrict__ zout)
{
    const int bh = blockIdx.y;
    const int mBase = blockIdx.x * 128;
    const float* Pb = Pg + (size_t)bh * Nc * Nc;
    const float* zi = zin + (size_t)bh * Nc * HD;

    __shared__ float Ps[128][36];
    __shared__ float Zs[32][72];

    const int tid = threadIdx.x;
    const int wid = tid >> 5, lane = tid & 31;
    const int g = lane >> 2, t = lane & 3;
    const int warpM = (wid >> 1) * 32;
    const int warpN = (wid & 1) * 32;

    float acc[2][4][4] = {};

    for (int k0 = 0; k0 < Nc; k0 += 32) {
        #pragma unroll
        for (int it = 0; it < 4; it++) {
            int j = tid + it * 256;
            int r = j >> 3, c4 = (j & 7) * 4;
            *(float4*)&Ps[r][c4] = *(const float4*)&Pb[(size_t)(mBase + r) * Nc + k0 + c4];
        }
        #pragma unroll
        for (int it = 0; it < 2; it++) {
            int j = tid + it * 256;
            int r = j >> 4, c4 = (j & 15) * 4;
            *(float4*)&Zs[r][c4] = *(const float4*)&zi[(size_t)(k0 + r) * HD + c4];
        }
        __syncthreads();
        #pragma unroll
        for (int ks = 0; ks < 32; ks += 8) {
            unsigned a[2][4], bb[4][2];
            #pragma unroll
            for (int mf = 0; mf < 2; mf++) {
                int r0 = warpM + mf * 16 + g;
                a[mf][0] = f2tf(Ps[r0][ks + t]);
                a[mf][1] = f2tf(Ps[r0 + 8][ks + t]);
                a[mf][2] = f2tf(Ps[r0][ks + t + 4]);
                a[mf][3] = f2tf(Ps[r0 + 8][ks + t + 4]);
            }
            #pragma unroll
            for (int nf = 0; nf < 4; nf++) {
                int nc = warpN + nf * 8 + g;
                bb[nf][0] = f2tf(Zs[ks + t][nc]);
                bb[nf][1] = f2tf(Zs[ks + t + 4][nc]);
            }
            #pragma unroll
            for (int mf = 0; mf < 2; mf++)
                #pragma unroll
                for (int nf = 0; nf < 4; nf++)
                    mma_tf32(acc[mf][nf], a[mf][0], a[mf][1], a[mf][2], a[mf][3],
                             bb[nf][0], bb[nf][1]);
        }
        __syncthreads();
    }

    #pragma unroll
    for (int mf = 0; mf < 2; mf++)
        #pragma unroll
        for (int half = 0; half < 2; half++) {
            int row = mBase + warpM + mf * 16 + g + half * 8;
            float scale = 0.9f / rowsum[(size_t)bh * Nc + row];
            const float* z0r = zinit + ((size_t)bh * Nc + row) * HD;
            float* zor = zout + ((size_t)bh * Nc + row) * HD;
            #pragma unroll
            for (int nf = 0; nf < 4; nf++) {
                int col = warpN + nf * 8 + 2 * t;
                float v0 = acc[mf][nf][half * 2 + 0] * scale + 0.1f * z0r[col];
                float v1 = acc[mf][nf][half * 2 + 1] * scale + 0.1f * z0r[col + 1];
                *(float2*)&zor[col] = make_float2(v0, v1);
            }
        }
}

// ---------------- kernel 4: residual + layernorm -----------------------------
__global__ __launch_bounds__(256) void out_kernel(
    const float* __restrict__ x, const float* __restrict__ z,
    const float* __restrict__ gamma, const float* __restrict__ beta,
    float* __restrict__ out)
{
    const int row = blockIdx.x;          // b*N + n
    const int b = row >> 10, n = row & (Nc - 1);
    const int t = threadIdx.x;
    __shared__ float red[256];

    float y[2];
    float s = 0.f;
    #pragma unroll
    for (int j = 0; j < 2; j++) {
        int idx = t + j * 256;
        int h = idx >> 6, d = idx & 63;
        y[j] = x[(size_t)row * Hc + idx] +
               z[(((size_t)b * NHEADS + h) * Nc + n) * HD + d];
        s += y[j];
    }
    red[t] = s; __syncthreads();
    #pragma unroll
    for (int st = 128; st > 0; st >>= 1) {
        if (t < st) red[t] += red[t + st];
        __syncthreads();
    }
    float mu = red[0] * (1.0f / Hc);
    __syncthreads();

    float vs = 0.f;
    #pragma unroll
    for (int j = 0; j < 2; j++) { float d0 = y[j] - mu; vs += d0 * d0; }
    red[t] = vs; __syncthreads();
    #pragma unroll
    for (int st = 128; st > 0; st >>= 1) {
        if (t < st) red[t] += red[t + st];
        __syncthreads();
    }
    float var = red[0] * (1.0f / Hc);
    float rstd = rsqrtf(var + LN_EPS);
    #pragma unroll
    for (int j = 0; j < 2; j++) {
        int idx = t + j * 256;
        out[(size_t)row * Hc + idx] = (y[j] - mu) * rstd * gamma[idx] + beta[idx];
    }
}

// ---------------- launch -----------------------------------------------------
extern "C" void kernel_launch(void* const* d_in, const int* in_sizes, int n_in,
                              void* d_out, int out_size)
{
    const float* x     = (const float*)d_in[0];
    const int*   adj   = (const int*)d_in[1];
    const float* Wq    = (const float*)d_in[2];
    const float* bq    = (const float*)d_in[3];
    const float* Wk    = (const float*)d_in[4];
    const float* bk    = (const float*)d_in[5];
    const float* Wv    = (const float*)d_in[6];
    const float* bv    = (const float*)d_in[7];
    const float* gamma = (const float*)d_in[8];
    const float* beta  = (const float*)d_in[9];
    float* out = (float*)d_out;

    float *pq, *pk, *pz0, *pP, *prs, *pzA, *pzB;
    cudaGetSymbolAddress((void**)&pq,  g_q);
    cudaGetSymbolAddress((void**)&pk,  g_k);
    cudaGetSymbolAddress((void**)&pz0, g_z0);
    cudaGetSymbolAddress((void**)&pP,  g_P);
    cudaGetSymbolAddress((void**)&prs, g_rowsum);
    cudaGetSymbolAddress((void**)&pzA, g_zA);
    cudaGetSymbolAddress((void**)&pzB, g_zB);

    cudaMemsetAsync(prs, 0, (size_t)Bc * NHEADS * Nc * sizeof(float));

    qkv_kernel<<<dim3(Hc / 64, (Bc * Nc) / 128, 3), 256>>>(
        x, Wq, bq, Wk, bk, Wv, bv, pq, pk, pz0);

    scores_kernel<<<dim3(Nc / 128, Nc / 128, Bc * NHEADS), 256>>>(
        pq, pk, adj, pP, prs);

    dim3 gHop(Nc / 128, Bc * NHEADS);
    hop_kernel<<<gHop, 256>>>(pP, prs, pz0, pz0, pzA);
    hop_kernel<<<gHop, 256>>>(pP, prs, pzA, pz0, pzB);
    hop_kernel<<<gHop, 256>>>(pP, prs, pzB, pz0, pzA);
    hop_kernel<<<gHop, 256>>>(pP, prs, pzA, pz0, pzB);

    out_kernel<<<Bc * Nc, 256>>>(x, pzB, gamma, beta, out);
}

// round 3
// speedup vs baseline: 4.2841x; 1.5490x over previous
#include <cuda_runtime.h>
#include <cuda_bf16.h>
#include <cstdint>

#define Bc 8
#define Nc 1024
#define Hc 512
#define NHEADS 8
#define HD 64
#define LN_EPS 1e-5f

typedef __nv_bfloat16 bf16;

// ---------------- scratch (allocation-free rule: __device__ globals) ----------
__device__ float g_q[Bc * NHEADS * Nc * HD];             // head-major [bh][n][d] fp32
__device__ float g_k[Bc * NHEADS * Nc * HD];
__device__ bf16  g_z0[Bc * NHEADS * HD * Nc];            // v, d-major [bh][d][n]
__device__ bf16  g_P[(size_t)Bc * NHEADS * Nc * Nc];     // exp(scores), bf16 (128MB)
__device__ float g_rowsum[Bc * NHEADS * Nc];
__device__ bf16  g_zA[Bc * NHEADS * HD * Nc];            // d-major
__device__ bf16  g_zC[Bc * NHEADS * HD * Nc];            // d-major
__device__ float g_zB[Bc * NHEADS * Nc * HD];            // final, token-major fp32

// ---------------- helpers ------------------------------------------------------
__device__ __forceinline__ unsigned f2tf(float x) {
    unsigned r;
    asm("cvt.rna.tf32.f32 %0, %1;" : "=r"(r) : "f"(x));
    return r;
}
__device__ __forceinline__ void mma_tf32(float c[4],
    unsigned a0, unsigned a1, unsigned a2, unsigned a3,
    unsigned b0, unsigned b1)
{
    asm("mma.sync.aligned.m16n8k8.row.col.f32.tf32.tf32.f32 "
        "{%0,%1,%2,%3},{%4,%5,%6,%7},{%8,%9},{%0,%1,%2,%3};"
        : "+f"(c[0]), "+f"(c[1]), "+f"(c[2]), "+f"(c[3])
        : "r"(a0), "r"(a1), "r"(a2), "r"(a3), "r"(b0), "r"(b1));
}
__device__ __forceinline__ void mma_bf16(float c[4],
    unsigned a0, unsigned a1, unsigned a2, unsigned a3,
    unsigned b0, unsigned b1)
{
    asm("mma.sync.aligned.m16n8k16.row.col.f32.bf16.bf16.f32 "
        "{%0,%1,%2,%3},{%4,%5,%6,%7},{%8,%9},{%0,%1,%2,%3};"
        : "+f"(c[0]), "+f"(c[1]), "+f"(c[2]), "+f"(c[3])
        : "r"(a0), "r"(a1), "r"(a2), "r"(a3), "r"(b0), "r"(b1));
}
__device__ __forceinline__ void cp16(unsigned smem_dst, const void* gsrc) {
    asm volatile("cp.async.cg.shared.global [%0], [%1], 16;"
                 :: "r"(smem_dst), "l"(gsrc));
}
__device__ __forceinline__ void cp_commit() {
    asm volatile("cp.async.commit_group;");
}
template<int N> __device__ __forceinline__ void cp_wait() {
    asm volatile("cp.async.wait_group %0;" :: "n"(N));
}

// ---------------- kernel 1: fused QKV GEMM ------------------------------------
// q,k -> head-major fp32 [bh][n][d]; v -> d-major bf16 [bh][d][n]
__global__ __launch_bounds__(256) void qkv_kernel(
    const float* __restrict__ X,
    const float* __restrict__ Wq, const float* __restrict__ bq,
    const float* __restrict__ Wk, const float* __restrict__ bk,
    const float* __restrict__ Wv, const float* __restrict__ bv,
    float* __restrict__ outq, float* __restrict__ outk, bf16* __restrict__ outv)
{
    const int which = blockIdx.z;
    const float* W    = which == 0 ? Wq : which == 1 ? Wk : Wv;
    const float* bias = which == 0 ? bq : which == 1 ? bk : bv;

    __shared__ float Xs[128][36];
    __shared__ float Ws[64][36];

    const int tid = threadIdx.x;
    const int wid = tid >> 5, lane = tid & 31;
    const int g = lane >> 2, t = lane & 3;
    const int warpM = (wid >> 1) * 32;
    const int warpN = (wid & 1) * 32;
    const int mBase = blockIdx.y * 128;
    const int nBase = blockIdx.x * 64;

    float acc[2][4][4] = {};

    for (int k0 = 0; k0 < Hc; k0 += 32) {
        #pragma unroll
        for (int it = 0; it < 4; it++) {
            int j = tid + it * 256;
            int r = j >> 3, c4 = (j & 7) * 4;
            *(float4*)&Xs[r][c4] = *(const float4*)&X[(size_t)(mBase + r) * Hc + k0 + c4];
        }
        #pragma unroll
        for (int it = 0; it < 2; it++) {
            int j = tid + it * 256;
            int r = j >> 3, c4 = (j & 7) * 4;
            *(float4*)&Ws[r][c4] = *(const float4*)&W[(size_t)(nBase + r) * Hc + k0 + c4];
        }
        __syncthreads();
        #pragma unroll
        for (int ks = 0; ks < 32; ks += 8) {
            unsigned a[2][4], b[4][2];
            #pragma unroll
            for (int mf = 0; mf < 2; mf++) {
                int r0 = warpM + mf * 16 + g;
                a[mf][0] = f2tf(Xs[r0][ks + t]);
                a[mf][1] = f2tf(Xs[r0 + 8][ks + t]);
                a[mf][2] = f2tf(Xs[r0][ks + t + 4]);
                a[mf][3] = f2tf(Xs[r0 + 8][ks + t + 4]);
            }
            #pragma unroll
            for (int nf = 0; nf < 4; nf++) {
                int nr = warpN + nf * 8 + g;
                b[nf][0] = f2tf(Ws[nr][ks + t]);
                b[nf][1] = f2tf(Ws[nr][ks + t + 4]);
            }
            #pragma unroll
            for (int mf = 0; mf < 2; mf++)
                #pragma unroll
                for (int nf = 0; nf < 4; nf++)
                    mma_tf32(acc[mf][nf], a[mf][0], a[mf][1], a[mf][2], a[mf][3],
                             b[nf][0], b[nf][1]);
        }
        __syncthreads();
    }

    #pragma unroll
    for (int mf = 0; mf < 2; mf++)
        #pragma unroll
        for (int nf = 0; nf < 4; nf++)
            #pragma unroll
            for (int e = 0; e < 4; e++) {
                int row = mBase + warpM + mf * 16 + g + ((e >> 1) * 8);
                int col = nBase + warpN + nf * 8 + 2 * t + (e & 1);
                float val = acc[mf][nf][e] + bias[col];
                int btok = row >> 10, ntok = row & 1023;
                int h = col >> 6, d = col & 63;
                int bh = btok * NHEADS + h;
                if (which == 2) {
                    outv[((size_t)bh * HD + d) * Nc + ntok] = __float2bfloat16_rn(val);
                } else {
                    float* out = which == 0 ? outq : outk;
                    out[((size_t)bh * Nc + ntok) * HD + d] = val;
                }
            }
}

// ---------------- kernel 2: scores -> masked exp (bf16) + rowsum --------------
__global__ __launch_bounds__(256) void scores_kernel(
    const float* __restrict__ q, const float* __restrict__ k,
    const int* __restrict__ adj, bf16* __restrict__ P,
    float* __restrict__ rowsum)
{
    const int bh = blockIdx.z;
    const int b = bh >> 3;
    const int nBase = blockIdx.y * 128;
    const int mBase = blockIdx.x * 128;

    __shared__ float Qs[128][36];
    __shared__ float Ks[128][36];

    const int tid = threadIdx.x;
    const int wid = tid >> 5, lane = tid & 31;
    const int g = lane >> 2, t = lane & 3;
    const int warpM = (wid >> 2) * 64;
    const int warpN = (wid & 3) * 32;

    const float* qb = q + (size_t)bh * Nc * HD;
    const float* kb = k + (size_t)bh * Nc * HD;

    float acc[4][4][4] = {};

    for (int k0 = 0; k0 < HD; k0 += 32) {
        #pragma unroll
        for (int it = 0; it < 4; it++) {
            int j = tid + it * 256;
            int r = j >> 3, c4 = (j & 7) * 4;
            *(float4*)&Qs[r][c4] = *(const float4*)&qb[(size_t)(nBase + r) * HD + k0 + c4];
            *(float4*)&Ks[r][c4] = *(const float4*)&kb[(size_t)(mBase + r) * HD + k0 + c4];
        }
        __syncthreads();
        #pragma unroll
        for (int ks = 0; ks < 32; ks += 8) {
            unsigned a[4][4], bb[4][2];
            #pragma unroll
            for (int mf = 0; mf < 4; mf++) {
                int r0 = warpM + mf * 16 + g;
                a[mf][0] = f2tf(Qs[r0][ks + t]);
                a[mf][1] = f2tf(Qs[r0 + 8][ks + t]);
                a[mf][2] = f2tf(Qs[r0][ks + t + 4]);
                a[mf][3] = f2tf(Qs[r0 + 8][ks + t + 4]);
            }
            #pragma unroll
            for (int nf = 0; nf < 4; nf++) {
                int nr = warpN + nf * 8 + g;
                bb[nf][0] = f2tf(Ks[nr][ks + t]);
                bb[nf][1] = f2tf(Ks[nr][ks + t + 4]);
            }
            #pragma unroll
            for (int mf = 0; mf < 4; mf++)
                #pragma unroll
                for (int nf = 0; nf < 4; nf++)
                    mma_tf32(acc[mf][nf], a[mf][0], a[mf][1], a[mf][2], a[mf][3],
                             bb[nf][0], bb[nf][1]);
        }
        __syncthreads();
    }

    const int* adjb = adj + (size_t)b * Nc * Nc;
    bf16* Pb = P + (size_t)bh * Nc * Nc;

    #pragma unroll
    for (int mf = 0; mf < 4; mf++) {
        #pragma unroll
        for (int half = 0; half < 2; half++) {
            int row = nBase + warpM + mf * 16 + g + half * 8;
            float local = 0.f;
            #pragma unroll
            for (int nf = 0; nf < 4; nf++) {
                int col = mBase + warpN + nf * 8 + 2 * t;
                float s0 = acc[mf][nf][half * 2 + 0];
                float s1 = acc[mf][nf][half * 2 + 1];
                int a0 = adjb[(size_t)row * Nc + col];
                int a1 = adjb[(size_t)row * Nc + col + 1];
                float e0 = a0 ? __expf(s0) : 0.f;
                float e1 = a1 ? __expf(s1) : 0.f;
                __nv_bfloat162 pr;
                pr.x = __float2bfloat16_rn(e0);
                pr.y = __float2bfloat16_rn(e1);
                *(__nv_bfloat162*)&Pb[(size_t)row * Nc + col] = pr;
                local += e0 + e1;
            }
            local += __shfl_xor_sync(0xffffffffu, local, 1);
            local += __shfl_xor_sync(0xffffffffu, local, 2);
            if (t == 0) atomicAdd(&rowsum[(size_t)bh * Nc + row], local);
        }
    }
}

// ---------------- kernel 3: hop, bf16 MMA, z resident in smem -----------------
// z buffers d-major [bh][d][n] bf16. LAST hop writes token-major fp32.
#define ZS_STRIDE_W 516            // (1024+8) bf16 per row -> 516 u32 words
#define ZS_BYTES (HD * ZS_STRIDE_W * 4)           // 132096
#define PS_STRIDE_W 36             // (64+8) bf16 per row -> 36 u32 words
#define PS_BUF_W (128 * PS_STRIDE_W)              // words per stage
#define PS_BYTES (2 * PS_BUF_W * 4)               // 36864
#define HOP_SMEM (ZS_BYTES + PS_BYTES)            // 168960

template<bool LAST>
__global__ __launch_bounds__(256) void hop_kernel2(
    const bf16* __restrict__ Pg, const float* __restrict__ rowsum,
    const bf16* __restrict__ zin_tr, const bf16* __restrict__ z0_tr,
    void* __restrict__ zout)
{
    extern __shared__ __align__(16) char smem[];
    unsigned sbase = (unsigned)__cvta_generic_to_shared(smem);
    const uint32_t* zsw = (const uint32_t*)smem;
    const uint32_t* psw = (const uint32_t*)(smem + ZS_BYTES);

    const int bh = blockIdx.y;
    const int mBase = blockIdx.x * 128;
    const bf16* Pb = Pg + (size_t)bh * Nc * Nc;
    const bf16* zi = zin_tr + (size_t)bh * HD * Nc;

    const int tid = threadIdx.x;
    const int wid = tid >> 5, lane = tid & 31;
    const int g = lane >> 2, t = lane & 3;
    const int warpM = (wid >> 1) * 32;
    const int warpN = (wid & 1) * 32;

    // ---- prologue: z slab (64 x 1024 bf16, rows padded) via cp.async ----
    #pragma unroll 4
    for (int j = 0; j < 32; j++) {
        int c = tid + j * 256;                 // 8192 chunks of 16B
        int d = c >> 7, off = c & 127;
        cp16(sbase + d * (ZS_STRIDE_W * 4) + off * 16, zi + (size_t)d * Nc + off * 8);
    }
    cp_commit();                               // G0: z
    // P stage 0
    #pragma unroll
    for (int j = 0; j < 4; j++) {
        int c = tid + j * 256;
        int r = c >> 3, off = c & 7;
        cp16(sbase + ZS_BYTES + r * (PS_STRIDE_W * 4) + off * 16,
             Pb + (size_t)(mBase + r) * Nc + off * 8);
    }
    cp_commit();                               // G1: P0
    // P stage 1
    #pragma unroll
    for (int j = 0; j < 4; j++) {
        int c = tid + j * 256;
        int r = c >> 3, off = c & 7;
        cp16(sbase + ZS_BYTES + PS_BUF_W * 4 + r * (PS_STRIDE_W * 4) + off * 16,
             Pb + (size_t)(mBase + r) * Nc + 64 + off * 8);
    }
    cp_commit();                               // G2: P1

    float acc[2][4][4] = {};

    #pragma unroll
    for (int it = 0; it < 16; it++) {          // K chunks of 64
        if (it < 15) cp_wait<1>(); else cp_wait<0>();
        __syncthreads();
        const int buf = it & 1;
        const uint32_t* pb = psw + buf * PS_BUF_W;
        const int kw0 = it * 32;
        #pragma unroll
        for (int ksw = 0; ksw < 32; ksw += 8) {
            unsigned a[2][4], bb[4][2];
            #pragma unroll
            for (int mf = 0; mf < 2; mf++) {
                int r0 = warpM + mf * 16 + g;
                a[mf][0] = pb[r0 * PS_STRIDE_W + ksw + t];
                a[mf][1] = pb[(r0 + 8) * PS_STRIDE_W + ksw + t];
                a[mf][2] = pb[r0 * PS_STRIDE_W + ksw + t + 4];
                a[mf][3] = pb[(r0 + 8) * PS_STRIDE_W + ksw + t + 4];
            }
            #pragma unroll
            for (int nf = 0; nf < 4; nf++) {
                int n = warpN + nf * 8 + g;
                bb[nf][0] = zsw[n * ZS_STRIDE_W + kw0 + ksw + t];
                bb[nf][1] = zsw[n * ZS_STRIDE_W + kw0 + ksw + t + 4];
            }
            #pragma unroll
            for (int mf = 0; mf < 2; mf++)
                #pragma unroll
                for (int nf = 0; nf < 4; nf++)
                    mma_bf16(acc[mf][nf], a[mf][0], a[mf][1], a[mf][2], a[mf][3],
                             bb[nf][0], bb[nf][1]);
        }
        __syncthreads();
        if (it + 2 < 16) {
            #pragma unroll
            for (int j = 0; j < 4; j++) {
                int c = tid + j * 256;
                int r = c >> 3, off = c & 7;
                cp16(sbase + ZS_BYTES + buf * (PS_BUF_W * 4) + r * (PS_STRIDE_W * 4) + off * 16,
                     Pb + (size_t)(mBase + r) * Nc + (it + 2) * 64 + off * 8);
            }
            cp_commit();
        }
    }

    // ---- epilogue ----
    #pragma unroll
    for (int mf = 0; mf < 2; mf++)
        #pragma unroll
        for (int half = 0; half < 2; half++) {
            int row = mBase + warpM + mf * 16 + g + half * 8;
            float scale = 0.9f / rowsum[(size_t)bh * Nc + row];
            #pragma unroll
            for (int nf = 0; nf < 4; nf++) {
                int col = warpN + nf * 8 + 2 * t;
                float z00 = __bfloat162float(z0_tr[((size_t)bh * HD + col) * Nc + row]);
                float z01 = __bfloat162float(z0_tr[((size_t)bh * HD + col + 1) * Nc + row]);
                float v0 = acc[mf][nf][half * 2 + 0] * scale + 0.1f * z00;
                float v1 = acc[mf][nf][half * 2 + 1] * scale + 0.1f * z01;
                if (LAST) {
                    float* zf = (float*)zout;
                    *(float2*)&zf[((size_t)bh * Nc + row) * HD + col] = make_float2(v0, v1);
                } else {
                    bf16* zo = (bf16*)zout;
                    zo[((size_t)bh * HD + col) * Nc + row] = __float2bfloat16_rn(v0);
                    zo[((size_t)bh * HD + col + 1) * Nc + row] = __float2bfloat16_rn(v1);
                }
            }
        }
}

// ---------------- kernel 4: residual + layernorm ------------------------------
__global__ __launch_bounds__(256) void out_kernel(
    const float* __restrict__ x, const float* __restrict__ z,
    const float* __restrict__ gamma, const float* __restrict__ beta,
    float* __restrict__ out)
{
    const int row = blockIdx.x;
    const int b = row >> 10, n = row & (Nc - 1);
    const int t = threadIdx.x;
    __shared__ float red[256];

    float y[2];
    float s = 0.f;
    #pragma unroll
    for (int j = 0; j < 2; j++) {
        int idx = t + j * 256;
        int h = idx >> 6, d = idx & 63;
        y[j] = x[(size_t)row * Hc + idx] +
               z[(((size_t)b * NHEADS + h) * Nc + n) * HD + d];
        s += y[j];
    }
    red[t] = s; __syncthreads();
    #pragma unroll
    for (int st = 128; st > 0; st >>= 1) {
        if (t < st) red[t] += red[t + st];
        __syncthreads();
    }
    float mu = red[0] * (1.0f / Hc);
    __syncthreads();

    float vs = 0.f;
    #pragma unroll
    for (int j = 0; j < 2; j++) { float d0 = y[j] - mu; vs += d0 * d0; }
    red[t] = vs; __syncthreads();
    #pragma unroll
    for (int st = 128; st > 0; st >>= 1) {
        if (t < st) red[t] += red[t + st];
        __syncthreads();
    }
    float var = red[0] * (1.0f / Hc);
    float rstd = rsqrtf(var + LN_EPS);
    #pragma unroll
    for (int j = 0; j < 2; j++) {
        int idx = t + j * 256;
        out[(size_t)row * Hc + idx] = (y[j] - mu) * rstd * gamma[idx] + beta[idx];
    }
}

// ---------------- launch -------------------------------------------------------
extern "C" void kernel_launch(void* const* d_in, const int* in_sizes, int n_in,
                              void* d_out, int out_size)
{
    const float* x     = (const float*)d_in[0];
    const int*   adj   = (const int*)d_in[1];
    const float* Wq    = (const float*)d_in[2];
    const float* bq    = (const float*)d_in[3];
    const float* Wk    = (const float*)d_in[4];
    const float* bk    = (const float*)d_in[5];
    const float* Wv    = (const float*)d_in[6];
    const float* bv    = (const float*)d_in[7];
    const float* gamma = (const float*)d_in[8];
    const float* beta  = (const float*)d_in[9];
    float* out = (float*)d_out;

    float *pq, *pk, *prs, *pzB;
    bf16 *pz0, *pP, *pzA, *pzC;
    cudaGetSymbolAddress((void**)&pq,  g_q);
    cudaGetSymbolAddress((void**)&pk,  g_k);
    cudaGetSymbolAddress((void**)&pz0, g_z0);
    cudaGetSymbolAddress((void**)&pP,  g_P);
    cudaGetSymbolAddress((void**)&prs, g_rowsum);
    cudaGetSymbolAddress((void**)&pzA, g_zA);
    cudaGetSymbolAddress((void**)&pzC, g_zC);
    cudaGetSymbolAddress((void**)&pzB, g_zB);

    cudaFuncSetAttribute(hop_kernel2<false>,
        cudaFuncAttributeMaxDynamicSharedMemorySize, HOP_SMEM);
    cudaFuncSetAttribute(hop_kernel2<true>,
        cudaFuncAttributeMaxDynamicSharedMemorySize, HOP_SMEM);

    cudaMemsetAsync(prs, 0, (size_t)Bc * NHEADS * Nc * sizeof(float));

    qkv_kernel<<<dim3(Hc / 64, (Bc * Nc) / 128, 3), 256>>>(
        x, Wq, bq, Wk, bk, Wv, bv, pq, pk, pz0);

    scores_kernel<<<dim3(Nc / 128, Nc / 128, Bc * NHEADS), 256>>>(
        pq, pk, adj, pP, prs);

    dim3 gHop(Nc / 128, Bc * NHEADS);
    hop_kernel2<false><<<gHop, 256, HOP_SMEM>>>(pP, prs, pz0, pz0, pzA);
    hop_kernel2<false><<<gHop, 256, HOP_SMEM>>>(pP, prs, pzA, pz0, pzC);
    hop_kernel2<false><<<gHop, 256, HOP_SMEM>>>(pP, prs, pzC, pz0, pzA);
    hop_kernel2<true><<<gHop, 256, HOP_SMEM>>>(pP, prs, pzA, pz0, pzB);

    out_kernel<<<Bc * Nc, 256>>>(x, pzB, gamma, beta, out);
}

// round 4
// speedup vs baseline: 5.1518x; 1.2025x over previous
#include <cuda_runtime.h>
#include <cuda_bf16.h>
#include <cstdint>

#define Bc 8
#define Nc 1024
#define Hc 512
#define NHEADS 8
#define HD 64
#define LN_EPS 1e-5f

typedef __nv_bfloat16 bf16;

// ---------------- scratch (allocation-free rule: __device__ globals) ----------
__device__ float g_q[Bc * NHEADS * Nc * HD];             // head-major [bh][n][d] fp32
__device__ float g_k[Bc * NHEADS * Nc * HD];
__device__ bf16  g_z0[Bc * NHEADS * HD * Nc];            // v, d-major [bh][d][n]
__device__ bf16  g_P[(size_t)Bc * NHEADS * Nc * Nc];     // exp(scores), bf16 (128MB)
__device__ float g_rowsum[Bc * NHEADS * Nc];
__device__ bf16  g_zA[Bc * NHEADS * HD * Nc];            // d-major
__device__ bf16  g_zC[Bc * NHEADS * HD * Nc];            // d-major
__device__ float g_zB[Bc * NHEADS * Nc * HD];            // final, token-major fp32

// ---------------- helpers ------------------------------------------------------
__device__ __forceinline__ unsigned f2tf(float x) {
    unsigned r;
    asm("cvt.rna.tf32.f32 %0, %1;" : "=r"(r) : "f"(x));
    return r;
}
__device__ __forceinline__ void mma_tf32(float c[4],
    unsigned a0, unsigned a1, unsigned a2, unsigned a3,
    unsigned b0, unsigned b1)
{
    asm("mma.sync.aligned.m16n8k8.row.col.f32.tf32.tf32.f32 "
        "{%0,%1,%2,%3},{%4,%5,%6,%7},{%8,%9},{%0,%1,%2,%3};"
        : "+f"(c[0]), "+f"(c[1]), "+f"(c[2]), "+f"(c[3])
        : "r"(a0), "r"(a1), "r"(a2), "r"(a3), "r"(b0), "r"(b1));
}
__device__ __forceinline__ void mma_bf16(float c[4],
    unsigned a0, unsigned a1, unsigned a2, unsigned a3,
    unsigned b0, unsigned b1)
{
    asm("mma.sync.aligned.m16n8k16.row.col.f32.bf16.bf16.f32 "
        "{%0,%1,%2,%3},{%4,%5,%6,%7},{%8,%9},{%0,%1,%2,%3};"
        : "+f"(c[0]), "+f"(c[1]), "+f"(c[2]), "+f"(c[3])
        : "r"(a0), "r"(a1), "r"(a2), "r"(a3), "r"(b0), "r"(b1));
}
__device__ __forceinline__ void cp16(unsigned smem_dst, const void* gsrc) {
    asm volatile("cp.async.cg.shared.global [%0], [%1], 16;"
                 :: "r"(smem_dst), "l"(gsrc));
}
__device__ __forceinline__ void cp_commit() {
    asm volatile("cp.async.commit_group;");
}
template<int N> __device__ __forceinline__ void cp_wait() {
    asm volatile("cp.async.wait_group %0;" :: "n"(N));
}

// ---------------- kernel 1: fused QKV GEMM ------------------------------------
// 128x128 output tile per CTA. q,k -> head-major fp32; v -> d-major bf16.
__global__ __launch_bounds__(256) void qkv_kernel(
    const float* __restrict__ X,
    const float* __restrict__ Wq, const float* __restrict__ bq,
    const float* __restrict__ Wk, const float* __restrict__ bk,
    const float* __restrict__ Wv, const float* __restrict__ bv,
    float* __restrict__ outq, float* __restrict__ outk, bf16* __restrict__ outv)
{
    const int which = blockIdx.z;
    const float* W    = which == 0 ? Wq : which == 1 ? Wk : Wv;
    const float* bias = which == 0 ? bq : which == 1 ? bk : bv;

    __shared__ float Xs[128][36];
    __shared__ float Ws[128][36];

    const int tid = threadIdx.x;
    const int wid = tid >> 5, lane = tid & 31;
    const int g = lane >> 2, t = lane & 3;
    const int warpM = (wid >> 1) * 32;
    const int warpN = (wid & 1) * 64;
    const int mBase = blockIdx.y * 128;
    const int nBase = blockIdx.x * 128;

    float acc[2][8][4] = {};

    for (int k0 = 0; k0 < Hc; k0 += 32) {
        #pragma unroll
        for (int it = 0; it < 4; it++) {
            int j = tid + it * 256;
            int r = j >> 3, c4 = (j & 7) * 4;
            *(float4*)&Xs[r][c4] = *(const float4*)&X[(size_t)(mBase + r) * Hc + k0 + c4];
            *(float4*)&Ws[r][c4] = *(const float4*)&W[(size_t)(nBase + r) * Hc + k0 + c4];
        }
        __syncthreads();
        #pragma unroll
        for (int ks = 0; ks < 32; ks += 8) {
            unsigned a[2][4], b[8][2];
            #pragma unroll
            for (int mf = 0; mf < 2; mf++) {
                int r0 = warpM + mf * 16 + g;
                a[mf][0] = f2tf(Xs[r0][ks + t]);
                a[mf][1] = f2tf(Xs[r0 + 8][ks + t]);
                a[mf][2] = f2tf(Xs[r0][ks + t + 4]);
                a[mf][3] = f2tf(Xs[r0 + 8][ks + t + 4]);
            }
            #pragma unroll
            for (int nf = 0; nf < 8; nf++) {
                int nr = warpN + nf * 8 + g;
                b[nf][0] = f2tf(Ws[nr][ks + t]);
                b[nf][1] = f2tf(Ws[nr][ks + t + 4]);
            }
            #pragma unroll
            for (int mf = 0; mf < 2; mf++)
                #pragma unroll
                for (int nf = 0; nf < 8; nf++)
                    mma_tf32(acc[mf][nf], a[mf][0], a[mf][1], a[mf][2], a[mf][3],
                             b[nf][0], b[nf][1]);
        }
        __syncthreads();
    }

    #pragma unroll
    for (int mf = 0; mf < 2; mf++)
        #pragma unroll
        for (int nf = 0; nf < 8; nf++)
            #pragma unroll
            for (int e = 0; e < 4; e++) {
                int row = mBase + warpM + mf * 16 + g + ((e >> 1) * 8);
                int col = nBase + warpN + nf * 8 + 2 * t + (e & 1);
                float val = acc[mf][nf][e] + bias[col];
                int btok = row >> 10, ntok = row & 1023;
                int h = col >> 6, d = col & 63;
                int bh = btok * NHEADS + h;
                if (which == 2) {
                    outv[((size_t)bh * HD + d) * Nc + ntok] = __float2bfloat16_rn(val);
                } else {
                    float* out = which == 0 ? outq : outk;
                    out[((size_t)bh * Nc + ntok) * HD + d] = val;
                }
            }
}

// ---------------- kernel 2: scores -> masked exp (bf16) + rowsum --------------
__global__ __launch_bounds__(256) void scores_kernel(
    const float* __restrict__ q, const float* __restrict__ k,
    const int* __restrict__ adj, bf16* __restrict__ P,
    float* __restrict__ rowsum)
{
    const int bh = blockIdx.z;
    const int b = bh >> 3;
    const int nBase = blockIdx.y * 128;
    const int mBase = blockIdx.x * 128;

    __shared__ float Qs[128][36];
    __shared__ float Ks[128][36];

    const int tid = threadIdx.x;
    const int wid = tid >> 5, lane = tid & 31;
    const int g = lane >> 2, t = lane & 3;
    const int warpM = (wid >> 2) * 64;
    const int warpN = (wid & 3) * 32;

    const float* qb = q + (size_t)bh * Nc * HD;
    const float* kb = k + (size_t)bh * Nc * HD;

    float acc[4][4][4] = {};

    for (int k0 = 0; k0 < HD; k0 += 32) {
        #pragma unroll
        for (int it = 0; it < 4; it++) {
            int j = tid + it * 256;
            int r = j >> 3, c4 = (j & 7) * 4;
            *(float4*)&Qs[r][c4] = *(const float4*)&qb[(size_t)(nBase + r) * HD + k0 + c4];
            *(float4*)&Ks[r][c4] = *(const float4*)&kb[(size_t)(mBase + r) * HD + k0 + c4];
        }
        __syncthreads();
        #pragma unroll
        for (int ks = 0; ks < 32; ks += 8) {
            unsigned a[4][4], bb[4][2];
            #pragma unroll
            for (int mf = 0; mf < 4; mf++) {
                int r0 = warpM + mf * 16 + g;
                a[mf][0] = f2tf(Qs[r0][ks + t]);
                a[mf][1] = f2tf(Qs[r0 + 8][ks + t]);
                a[mf][2] = f2tf(Qs[r0][ks + t + 4]);
                a[mf][3] = f2tf(Qs[r0 + 8][ks + t + 4]);
            }
            #pragma unroll
            for (int nf = 0; nf < 4; nf++) {
                int nr = warpN + nf * 8 + g;
                bb[nf][0] = f2tf(Ks[nr][ks + t]);
                bb[nf][1] = f2tf(Ks[nr][ks + t + 4]);
            }
            #pragma unroll
            for (int mf = 0; mf < 4; mf++)
                #pragma unroll
                for (int nf = 0; nf < 4; nf++)
                    mma_tf32(acc[mf][nf], a[mf][0], a[mf][1], a[mf][2], a[mf][3],
                             bb[nf][0], bb[nf][1]);
        }
        __syncthreads();
    }

    const int* adjb = adj + (size_t)b * Nc * Nc;
    bf16* Pb = P + (size_t)bh * Nc * Nc;

    #pragma unroll
    for (int mf = 0; mf < 4; mf++) {
        #pragma unroll
        for (int half = 0; half < 2; half++) {
            int row = nBase + warpM + mf * 16 + g + half * 8;
            float local = 0.f;
            #pragma unroll
            for (int nf = 0; nf < 4; nf++) {
                int col = mBase + warpN + nf * 8 + 2 * t;
                float s0 = acc[mf][nf][half * 2 + 0];
                float s1 = acc[mf][nf][half * 2 + 1];
                int a0 = adjb[(size_t)row * Nc + col];
                int a1 = adjb[(size_t)row * Nc + col + 1];
                float e0 = a0 ? __expf(s0) : 0.f;
                float e1 = a1 ? __expf(s1) : 0.f;
                __nv_bfloat162 pr;
                pr.x = __float2bfloat16_rn(e0);
                pr.y = __float2bfloat16_rn(e1);
                *(__nv_bfloat162*)&Pb[(size_t)row * Nc + col] = pr;
                local += e0 + e1;
            }
            local += __shfl_xor_sync(0xffffffffu, local, 1);
            local += __shfl_xor_sync(0xffffffffu, local, 2);
            if (t == 0) atomicAdd(&rowsum[(size_t)bh * Nc + row], local);
        }
    }
}

// ---------------- kernel 3: hop, K-chunked double-buffered, serpentine --------
// P chunk: 128 rows x 64 bf16 (stride 36 words). z chunk: 64 d-rows x 64 bf16.
#define PC_STRIDE 36
#define PC_W (128 * PC_STRIDE)                 // 4608 words
#define ZC_STRIDE 36
#define ZC_W (64 * ZC_STRIDE)                  // 2304 words
#define STAGE_W (PC_W + ZC_W)                  // 6912 words
#define HOP_SMEM (2 * STAGE_W * 4)             // 55296 bytes

template<bool LAST>
__global__ __launch_bounds__(256, 3) void hop_kernel3(
    const bf16* __restrict__ Pg, const float* __restrict__ rowsum,
    const bf16* __restrict__ zin_tr, const bf16* __restrict__ z0_tr,
    void* __restrict__ zout, int rev)
{
    extern __shared__ __align__(16) char smem[];
    unsigned sbase = (unsigned)__cvta_generic_to_shared(smem);
    const uint32_t* sw = (const uint32_t*)smem;

    int lin = blockIdx.y * gridDim.x + blockIdx.x;   // 0..511
    if (rev) lin = 511 - lin;
    const int bh = lin >> 3;
    const int mBase = (lin & 7) * 128;

    const bf16* Pb = Pg + (size_t)bh * Nc * Nc;
    const bf16* zi = zin_tr + (size_t)bh * HD * Nc;

    const int tid = threadIdx.x;
    const int wid = tid >> 5, lane = tid & 31;
    const int g = lane >> 2, t = lane & 3;
    const int warpM = (wid >> 1) * 32;
    const int warpN = (wid & 1) * 32;

    // load chunk `ck` into stage `s`
    auto load_chunk = [&](int ck, int s) {
        unsigned pbase = sbase + s * (STAGE_W * 4);
        unsigned zbase = pbase + PC_W * 4;
        const int k0 = ck * 64;
        #pragma unroll
        for (int j = 0; j < 4; j++) {
            int c = tid + j * 256;
            int r = c >> 3, off = c & 7;
            cp16(pbase + r * (PC_STRIDE * 4) + off * 16,
                 Pb + (size_t)(mBase + r) * Nc + k0 + off * 8);
        }
        #pragma unroll
        for (int j = 0; j < 2; j++) {
            int c = tid + j * 256;
            int d = c >> 3, off = c & 7;
            cp16(zbase + d * (ZC_STRIDE * 4) + off * 16,
                 zi + (size_t)d * Nc + k0 + off * 8);
        }
        cp_commit();
    };

    load_chunk(0, 0);
    load_chunk(1, 1);

    float acc[2][4][4] = {};

    #pragma unroll
    for (int it = 0; it < 16; it++) {
        if (it < 15) cp_wait<1>(); else cp_wait<0>();
        __syncthreads();
        const int buf = it & 1;
        const uint32_t* pc = sw + buf * STAGE_W;
        const uint32_t* zc = pc + PC_W;
        #pragma unroll
        for (int ksw = 0; ksw < 32; ksw += 8) {
            unsigned a[2][4], bb[4][2];
            #pragma unroll
            for (int mf = 0; mf < 2; mf++) {
                int r0 = warpM + mf * 16 + g;
                a[mf][0] = pc[r0 * PC_STRIDE + ksw + t];
                a[mf][1] = pc[(r0 + 8) * PC_STRIDE + ksw + t];
                a[mf][2] = pc[r0 * PC_STRIDE + ksw + t + 4];
                a[mf][3] = pc[(r0 + 8) * PC_STRIDE + ksw + t + 4];
            }
            #pragma unroll
            for (int nf = 0; nf < 4; nf++) {
                int n = warpN + nf * 8 + g;
                bb[nf][0] = zc[n * ZC_STRIDE + ksw + t];
                bb[nf][1] = zc[n * ZC_STRIDE + ksw + t + 4];
            }
            #pragma unroll
            for (int mf = 0; mf < 2; mf++)
                #pragma unroll
                for (int nf = 0; nf < 4; nf++)
                    mma_bf16(acc[mf][nf], a[mf][0], a[mf][1], a[mf][2], a[mf][3],
                             bb[nf][0], bb[nf][1]);
        }
        __syncthreads();
        if (it + 2 < 16) load_chunk(it + 2, buf);
    }

    // ---- epilogue ----
    #pragma unroll
    for (int mf = 0; mf < 2; mf++)
        #pragma unroll
        for (int half = 0; half < 2; half++) {
            int row = mBase + warpM + mf * 16 + g + half * 8;
            float scale = 0.9f / rowsum[(size_t)bh * Nc + row];
            #pragma unroll
            for (int nf = 0; nf < 4; nf++) {
                int col = warpN + nf * 8 + 2 * t;
                float z00 = __bfloat162float(z0_tr[((size_t)bh * HD + col) * Nc + row]);
                float z01 = __bfloat162float(z0_tr[((size_t)bh * HD + col + 1) * Nc + row]);
                float v0 = acc[mf][nf][half * 2 + 0] * scale + 0.1f * z00;
                float v1 = acc[mf][nf][half * 2 + 1] * scale + 0.1f * z01;
                if (LAST) {
                    float* zf = (float*)zout;
                    *(float2*)&zf[((size_t)bh * Nc + row) * HD + col] = make_float2(v0, v1);
                } else {
                    bf16* zo = (bf16*)zout;
                    zo[((size_t)bh * HD + col) * Nc + row] = __float2bfloat16_rn(v0);
                    zo[((size_t)bh * HD + col + 1) * Nc + row] = __float2bfloat16_rn(v1);
                }
            }
        }
}

// ---------------- kernel 4: residual + layernorm ------------------------------
__global__ __launch_bounds__(256) void out_kernel(
    const float* __restrict__ x, const float* __restrict__ z,
    const float* __restrict__ gamma, const float* __restrict__ beta,
    float* __restrict__ out)
{
    const int row = blockIdx.x;
    const int b = row >> 10, n = row & (Nc - 1);
    const int t = threadIdx.x;
    __shared__ float red[256];

    float y[2];
    float s = 0.f;
    #pragma unroll
    for (int j = 0; j < 2; j++) {
        int idx = t + j * 256;
        int h = idx >> 6, d = idx & 63;
        y[j] = x[(size_t)row * Hc + idx] +
               z[(((size_t)b * NHEADS + h) * Nc + n) * HD + d];
        s += y[j];
    }
    red[t] = s; __syncthreads();
    #pragma unroll
    for (int st = 128; st > 0; st >>= 1) {
        if (t < st) red[t] += red[t + st];
        __syncthreads();
    }
    float mu = red[0] * (1.0f / Hc);
    __syncthreads();

    float vs = 0.f;
    #pragma unroll
    for (int j = 0; j < 2; j++) { float d0 = y[j] - mu; vs += d0 * d0; }
    red[t] = vs; __syncthreads();
    #pragma unroll
    for (int st = 128; st > 0; st >>= 1) {
        if (t < st) red[t] += red[t + st];
        __syncthreads();
    }
    float var = red[0] * (1.0f / Hc);
    float rstd = rsqrtf(var + LN_EPS);
    #pragma unroll
    for (int j = 0; j < 2; j++) {
        int idx = t + j * 256;
        out[(size_t)row * Hc + idx] = (y[j] - mu) * rstd * gamma[idx] + beta[idx];
    }
}

// ---------------- launch -------------------------------------------------------
extern "C" void kernel_launch(void* const* d_in, const int* in_sizes, int n_in,
                              void* d_out, int out_size)
{
    const float* x     = (const float*)d_in[0];
    const int*   adj   = (const int*)d_in[1];
    const float* Wq    = (const float*)d_in[2];
    const float* bq    = (const float*)d_in[3];
    const float* Wk    = (const float*)d_in[4];
    const float* bk    = (const float*)d_in[5];
    const float* Wv    = (const float*)d_in[6];
    const float* bv    = (const float*)d_in[7];
    const float* gamma = (const float*)d_in[8];
    const float* beta  = (const float*)d_in[9];
    float* out = (float*)d_out;

    float *pq, *pk, *prs, *pzB;
    bf16 *pz0, *pP, *pzA, *pzC;
    cudaGetSymbolAddress((void**)&pq,  g_q);
    cudaGetSymbolAddress((void**)&pk,  g_k);
    cudaGetSymbolAddress((void**)&pz0, g_z0);
    cudaGetSymbolAddress((void**)&pP,  g_P);
    cudaGetSymbolAddress((void**)&prs, g_rowsum);
    cudaGetSymbolAddress((void**)&pzA, g_zA);
    cudaGetSymbolAddress((void**)&pzC, g_zC);
    cudaGetSymbolAddress((void**)&pzB, g_zB);

    cudaFuncSetAttribute(hop_kernel3<false>,
        cudaFuncAttributeMaxDynamicSharedMemorySize, HOP_SMEM);
    cudaFuncSetAttribute(hop_kernel3<true>,
        cudaFuncAttributeMaxDynamicSharedMemorySize, HOP_SMEM);

    cudaMemsetAsync(prs, 0, (size_t)Bc * NHEADS * Nc * sizeof(float));

    qkv_kernel<<<dim3(Hc / 128, (Bc * Nc) / 128, 3), 256>>>(
        x, Wq, bq, Wk, bk, Wv, bv, pq, pk, pz0);

    scores_kernel<<<dim3(Nc / 128, Nc / 128, Bc * NHEADS), 256>>>(
        pq, pk, adj, pP, prs);

    dim3 gHop(Nc / 128, Bc * NHEADS);
    // serpentine: scores wrote P forward -> hop1 reversed -> hop2 forward -> ...
    hop_kernel3<false><<<gHop, 256, HOP_SMEM>>>(pP, prs, pz0, pz0, pzA, 1);
    hop_kernel3<false><<<gHop, 256, HOP_SMEM>>>(pP, prs, pzA, pz0, pzC, 0);
    hop_kernel3<false><<<gHop, 256, HOP_SMEM>>>(pP, prs, pzC, pz0, pzA, 1);
    hop_kernel3<true><<<gHop, 256, HOP_SMEM>>>(pP, prs, pzA, pz0, pzB, 0);

    out_kernel<<<Bc * Nc, 256>>>(x, pzB, gamma, beta, out);
}